// round 7
// baseline (speedup 1.0000x reference)
#include <cuda_runtime.h>
#include <cuda_bf16.h>
#include <cstdint>

// Problem dims
#define N_INST 128
#define N_NOTES 88
#define BATCH 64
#define TLEN 201
#define FLEN 52
#define T2 197
#define F2 48
#define FEAT (T2 * F2)  // 9456
#define KC 48
#define NCHUNK 197

typedef unsigned long long ull;

// ---------------------------------------------------------------------------
// smem layout
// ---------------------------------------------------------------------------
#define WF32_STAGE 16896                   // 88 rows x 192B fp32 W
#define WF32_OFF 0
#define WB_OFF (4 * WF32_STAGE)            // 67584: bf16 W hi/lo double buffer
#define WB_STAGE 24576
#define WLO_REL 12288
#define X_OFF (WB_OFF + 2 * WB_STAGE)      // 116736: X hi/lo double buffer
#define X_STAGE 16384
#define XLO_REL 8192
#define SMEM_TOTAL (X_OFF + 2 * X_STAGE)   // 149504

// ---------------------------------------------------------------------------
// helpers
// ---------------------------------------------------------------------------
__device__ __forceinline__ uint32_t smem_u32(const void* p) {
    uint32_t a;
    asm("{ .reg .u64 t; cvta.to.shared.u64 t, %1; cvt.u32.u64 %0, t; }" : "=r"(a) : "l"(p));
    return a;
}
__device__ __forceinline__ unsigned swz(unsigned off) { return off ^ ((off >> 3) & 0x70); }

__device__ __forceinline__ void cp16g(uint32_t dst, const void* src) {
    asm volatile("cp.async.cg.shared.global [%0], [%1], 16;" :: "r"(dst), "l"(src) : "memory");
}
__device__ __forceinline__ void cp_commit() { asm volatile("cp.async.commit_group;" ::: "memory"); }
#define CP_WAIT(n) asm volatile("cp.async.wait_group %0;" :: "n"(n) : "memory")

__device__ __forceinline__ void ldsm4(unsigned r[4], uint32_t a) {
    asm volatile("ldmatrix.sync.aligned.m8n8.x4.shared.b16 {%0,%1,%2,%3}, [%4];"
                 : "=r"(r[0]), "=r"(r[1]), "=r"(r[2]), "=r"(r[3]) : "r"(a));
}
__device__ __forceinline__ void ldsm2(unsigned r[2], uint32_t a) {
    asm volatile("ldmatrix.sync.aligned.m8n8.x2.shared.b16 {%0,%1}, [%2];"
                 : "=r"(r[0]), "=r"(r[1]) : "r"(a));
}
__device__ __forceinline__ void mma_bf16(float c[4], const unsigned a[4], const unsigned* b) {
    asm volatile(
        "mma.sync.aligned.m16n8k16.row.col.f32.bf16.bf16.f32 "
        "{%0,%1,%2,%3}, {%4,%5,%6,%7}, {%8,%9}, {%0,%1,%2,%3};"
        : "+f"(c[0]), "+f"(c[1]), "+f"(c[2]), "+f"(c[3])
        : "r"(a[0]), "r"(a[1]), "r"(a[2]), "r"(a[3]), "r"(b[0]), "r"(b[1]));
}
__device__ __forceinline__ unsigned cvt_bf16x2(float lo, float hi) {
    unsigned d;
    asm("cvt.rn.bf16x2.f32 %0, %1, %2;" : "=r"(d) : "f"(hi), "f"(lo));
    return d;
}
__device__ __forceinline__ ull pack2(float lo, float hi) {
    ull r;
    asm("mov.b64 %0, {%1, %2};" : "=l"(r) : "f"(lo), "f"(hi));
    return r;
}
__device__ __forceinline__ void unpack2(ull v, float& lo, float& hi) {
    asm("mov.b64 {%0, %1}, %2;" : "=f"(lo), "=f"(hi) : "l"(v));
}
__device__ __forceinline__ ull ffma2(ull a, ull b, ull c) {
    ull d;
    asm("fma.rn.f32x2 %0, %1, %2, %3;" : "=l"(d) : "l"(a), "l"(b), "l"(c));
    return d;
}
__device__ __forceinline__ void sts64(uint32_t a, ull v) {
    asm volatile("st.shared.b64 [%0], %1;" :: "r"(a), "l"(v) : "memory");
}

// conv1 row rr (7 output pairs incl 2-col halo) -> conv2 accumulate-on-arrival.
// Slots: u[PH] = conv2 row rr (fresh), u[S1] = row rr-1, u[S2] = row rr-2 (emit).
template <int PH, int S1, int S2>
__device__ __forceinline__ void arrival(
    int rr, bool doemit, ull (&u)[3][6],
    const float* dptr, const ull* W1p, const ull* W2p, ull B1p, ull B2p,
    uint32_t xbase, int cb, int fg)
{
    ull v[7];
#pragma unroll
    for (int q = 0; q < 7; ++q) v[q] = B1p;
#pragma unroll
    for (int j = 0; j < 3; ++j) {
        const float* rp = dptr + (size_t)(rr + j) * FLEN;
        float4 A = *(const float4*)rp;
        float4 Bv = *(const float4*)(rp + 4);
        float4 Cv = *(const float4*)(rp + 8);
        float4 Dv = *(const float4*)(rp + 12);
        ull E[8], O[7];
        E[0] = pack2(A.x, A.y);  E[1] = pack2(A.z, A.w);
        E[2] = pack2(Bv.x, Bv.y); E[3] = pack2(Bv.z, Bv.w);
        E[4] = pack2(Cv.x, Cv.y); E[5] = pack2(Cv.z, Cv.w);
        E[6] = pack2(Dv.x, Dv.y); E[7] = pack2(Dv.z, Dv.w);
        O[0] = pack2(A.y, A.z);  O[1] = pack2(A.w, Bv.x);
        O[2] = pack2(Bv.y, Bv.z); O[3] = pack2(Bv.w, Cv.x);
        O[4] = pack2(Cv.y, Cv.z); O[5] = pack2(Cv.w, Dv.x);
        O[6] = pack2(Dv.y, Dv.z);
#pragma unroll
        for (int q = 0; q < 7; ++q) {
            v[q] = ffma2(W1p[3 * j + 0], E[q], v[q]);
            v[q] = ffma2(W1p[3 * j + 1], O[q], v[q]);
            v[q] = ffma2(W1p[3 * j + 2], E[q + 1], v[q]);
        }
    }
    // relu + rebuild E/O pair views of the conv1 row
    float f[14];
#pragma unroll
    for (int q = 0; q < 7; ++q) {
        unpack2(v[q], f[2 * q], f[2 * q + 1]);
        f[2 * q] = fmaxf(f[2 * q], 0.f);
        f[2 * q + 1] = fmaxf(f[2 * q + 1], 0.f);
    }
    ull pe[7], po[6];
#pragma unroll
    for (int q = 0; q < 7; ++q) pe[q] = pack2(f[2 * q], f[2 * q + 1]);
#pragma unroll
    for (int q = 0; q < 6; ++q) po[q] = pack2(f[2 * q + 1], f[2 * q + 2]);

#pragma unroll
    for (int q = 0; q < 6; ++q) {
        ull t = B2p;
        t = ffma2(W2p[0], pe[q], t);
        t = ffma2(W2p[1], po[q], t);
        t = ffma2(W2p[2], pe[q + 1], t);
        u[PH][q] = t;
        u[S1][q] = ffma2(W2p[3], pe[q], u[S1][q]);
        u[S1][q] = ffma2(W2p[4], po[q], u[S1][q]);
        u[S1][q] = ffma2(W2p[5], pe[q + 1], u[S1][q]);
        u[S2][q] = ffma2(W2p[6], pe[q], u[S2][q]);
        u[S2][q] = ffma2(W2p[7], po[q], u[S2][q]);
        u[S2][q] = ffma2(W2p[8], pe[q + 1], u[S2][q]);
    }
    if (doemit) {
        // conv2 row rr-2 complete: relu, hi/lo split, store to X tile
        const uint32_t xa = xbase + (((rr) - 2) & 1) * X_STAGE;
        unsigned hi[6], lo[6];
#pragma unroll
        for (int q = 0; q < 6; ++q) {
            float g0, g1;
            unpack2(u[S2][q], g0, g1);
            g0 = fmaxf(g0, 0.f); g1 = fmaxf(g1, 0.f);
            unsigned ub0 = __float_as_uint(g0), ub1 = __float_as_uint(g1);
            hi[q] = __byte_perm(ub0, ub1, 0x7632);
            float r0 = g0 - __uint_as_float(ub0 & 0xffff0000u);
            float r1 = g1 - __uint_as_float(ub1 & 0xffff0000u);
            lo[q] = cvt_bf16x2(r0, r1);
        }
#pragma unroll
        for (int r = 0; r < 3; ++r) {
            unsigned off = swz(cb * 128 + 24 * fg + 8 * r);
            sts64(xa + off, (ull)hi[2 * r] | ((ull)hi[2 * r + 1] << 32));
            sts64(xa + XLO_REL + off, (ull)lo[2 * r] | ((ull)lo[2 * r + 1] << 32));
        }
    }
}

// ---------------------------------------------------------------------------
// Fused warp-specialized kernel: one CTA / instrument, 512 threads.
// Warps 0-7: MMA consumers.  Warps 8-15: conv + W-pipeline producers.
// ---------------------------------------------------------------------------
__global__ __launch_bounds__(512, 1) void fused_kernel(
    const float* __restrict__ data,
    const float* __restrict__ w1, const float* __restrict__ b1,
    const float* __restrict__ w2, const float* __restrict__ b2,
    const float* __restrict__ wfc,
    const float* __restrict__ bfc,
    float* __restrict__ out)
{
    extern __shared__ char sm[];
    const uint32_t sbase = smem_u32(sm);
    const int i = blockIdx.x;
    const int tid = threadIdx.x;
    const int lane = tid & 31;
    const int wid = tid >> 5;
    const bool prod = wid >= 8;

    // consumer ids
    const int warp_m = (wid & 7) >> 2;
    const int warp_n = wid & 3;
    // producer ids
    const int ptid = tid & 255;
    const int cb = ptid >> 2;
    const int fg = ptid & 3;

    // zero bf16-W buffers (pad rows 88..95 stay zero forever)
    for (int o = tid * 16; o < 2 * WB_STAGE; o += 512 * 16)
        *(uint4*)(sm + WB_OFF + o) = make_uint4(0, 0, 0, 0);

    const float* Wp = wfc + (size_t)i * N_NOTES * FEAT;
    const float* dptr = data + (size_t)cb * TLEN * FLEN + 12 * fg;

    // producer conv state
    ull W1p[9], W2p[9];
    ull B1p = 0, B2p = 0;
    ull u[3][6];
    if (prod) {
#pragma unroll
        for (int k = 0; k < 9; ++k) {
            float a = w1[i * 9 + k]; W1p[k] = pack2(a, a);
            float c = w2[i * 9 + k]; W2p[k] = pack2(c, c);
        }
        float b1v = b1[i], b2v = b2[i];
        B1p = pack2(b1v, b1v);
        B2p = pack2(b2v, b2v);
#pragma unroll
        for (int s = 0; s < 3; ++s)
#pragma unroll
            for (int q = 0; q < 6; ++q) u[s][q] = 0;
    }

    // --- W pipeline (producers only) ---
    auto prefetchW = [&](int c) {
        const int k0 = c * KC;
        const uint32_t wdst = sbase + WF32_OFF + (c & 3) * WF32_STAGE;
#pragma unroll
        for (int s = 0; s < 4; ++s) {
            int idx = ptid + s * 256;
            cp16g(wdst + idx * 16, Wp + (size_t)(idx / 12) * FEAT + k0 + (idx % 12) * 4);
        }
        if (ptid < 32) {
            int idx = 1024 + ptid;
            cp16g(wdst + idx * 16, Wp + (size_t)(idx / 12) * FEAT + k0 + (idx % 12) * 4);
        }
    };
    auto convertW = [&](int c) {
        const char* src = sm + WF32_OFF + (c & 3) * WF32_STAGE;
        char* dhi = sm + WB_OFF + (c & 1) * WB_STAGE;
        char* dlo = dhi + WLO_REL;
#pragma unroll
        for (int s = 0; s < 5; ++s) {
            int idx = ptid + s * 256;
            if (idx < 1056) {
                int row = idx / 12, q = idx % 12;
                float4 v = *(const float4*)(src + idx * 16);
                unsigned ax = __float_as_uint(v.x), ay = __float_as_uint(v.y);
                unsigned az = __float_as_uint(v.z), aw = __float_as_uint(v.w);
                unsigned hi0 = __byte_perm(ax, ay, 0x7632);
                unsigned hi1 = __byte_perm(az, aw, 0x7632);
                float rx = v.x - __uint_as_float(ax & 0xffff0000u);
                float ry = v.y - __uint_as_float(ay & 0xffff0000u);
                float rz = v.z - __uint_as_float(az & 0xffff0000u);
                float rw = v.w - __uint_as_float(aw & 0xffff0000u);
                unsigned lo0 = cvt_bf16x2(rx, ry);
                unsigned lo1 = cvt_bf16x2(rz, rw);
                unsigned off = swz(row * 128 + q * 8);
                *(uint2*)(dhi + off) = make_uint2(hi0, hi1);
                *(uint2*)(dlo + off) = make_uint2(lo0, lo1);
            }
        }
    };

    // --- MMA state (consumers only) ---
    float acc[2][3][4];
#pragma unroll
    for (int mt = 0; mt < 2; ++mt)
#pragma unroll
        for (int nt = 0; nt < 3; ++nt)
#pragma unroll
            for (int r = 0; r < 4; ++r) acc[mt][nt][r] = 0.f;

    const int a_row = lane & 15;
    const int a_colb = (lane >> 4) << 4;
    const int b4_row = (lane & 7) + ((lane >> 4) << 3);
    const int b4_colb = ((lane >> 3) & 1) << 4;
    const int b2_row = lane & 7;
    const int b2_colb = ((lane >> 3) & 1) << 4;

    auto mma_step = [&](int c) {
        const uint32_t xb = sbase + X_OFF + (c & 1) * X_STAGE;
        const uint32_t wb = sbase + WB_OFF + (c & 1) * WB_STAGE;
#pragma unroll
        for (int ks = 0; ks < 3; ++ks) {
            const int kb = ks * 32;
            unsigned ahi[2][4], alo[2][4];
#pragma unroll
            for (int mt = 0; mt < 2; ++mt) {
                int m0 = warp_m * 32 + mt * 16;
                unsigned off = swz((m0 + a_row) * 128 + kb + a_colb);
                ldsm4(ahi[mt], xb + off);
                ldsm4(alo[mt], xb + XLO_REL + off);
            }
            const int n0 = warp_n * 24;
            unsigned bh[3][2], bl[3][2];
            unsigned off4 = swz((n0 + b4_row) * 128 + kb + b4_colb);
            ldsm4(&bh[0][0], wb + off4);
            ldsm4(&bl[0][0], wb + WLO_REL + off4);
            unsigned off2 = swz((n0 + 16 + b2_row) * 128 + kb + b2_colb);
            ldsm2(bh[2], wb + off2);
            ldsm2(bl[2], wb + WLO_REL + off2);
#pragma unroll
            for (int nt = 0; nt < 3; ++nt)
#pragma unroll
                for (int mt = 0; mt < 2; ++mt) {
                    mma_bf16(acc[mt][nt], ahi[mt], bh[nt]);
                    mma_bf16(acc[mt][nt], ahi[mt], bl[nt]);
                    mma_bf16(acc[mt][nt], alo[mt], bh[nt]);
                }
        }
    };

    // --- prologue (producers fill X(0), WB(0); 3 W stages in flight) ---
    if (prod) {
        prefetchW(0); cp_commit();
        prefetchW(1); cp_commit();
        prefetchW(2); cp_commit();
        arrival<0, 2, 1>(0, false, u, dptr, W1p, W2p, B1p, B2p, sbase + X_OFF, cb, fg);
        arrival<1, 0, 2>(1, false, u, dptr, W1p, W2p, B1p, B2p, sbase + X_OFF, cb, fg);
        arrival<2, 1, 0>(2, true,  u, dptr, W1p, W2p, B1p, B2p, sbase + X_OFF, cb, fg);
        CP_WAIT(2);
        convertW(0);
    }
    __syncthreads();

#define STEP(c, PH, S1, S2) do { \
    if (prod) { \
        if ((c) + 3 < NCHUNK) prefetchW((c) + 3); \
        cp_commit(); \
        arrival<PH, S1, S2>((c) + 3, true, u, dptr, W1p, W2p, B1p, B2p, sbase + X_OFF, cb, fg); \
        CP_WAIT(2); \
        if ((c) + 1 < NCHUNK) convertW((c) + 1); \
    } else { \
        mma_step(c); \
    } \
    __syncthreads(); \
} while (0)

    for (int c0 = 0; c0 < 195; c0 += 3) {
        STEP(c0 + 0, 0, 2, 1);
        STEP(c0 + 1, 1, 0, 2);
        STEP(c0 + 2, 2, 1, 0);
    }
    STEP(195, 0, 2, 1);
    // final chunk: no more conv / convert work
    if (prod) { cp_commit(); CP_WAIT(0); }
    else      { mma_step(196); }
    __syncthreads();
#undef STEP

    // --- epilogue (consumers): bias + sigmoid + store out[b][i][n] ---
    if (!prod) {
#pragma unroll
        for (int mt = 0; mt < 2; ++mt) {
            int b0 = warp_m * 32 + mt * 16 + (lane >> 2);
#pragma unroll
            for (int nt = 0; nt < 3; ++nt) {
                int n = warp_n * 24 + nt * 8 + 2 * (lane & 3);
                if (n < N_NOTES) {
                    float bi0 = bfc[i * N_NOTES + n];
                    float bi1 = bfc[i * N_NOTES + n + 1];
                    float s0 = acc[mt][nt][0] + bi0;
                    float s1 = acc[mt][nt][1] + bi1;
                    float s2 = acc[mt][nt][2] + bi0;
                    float s3 = acc[mt][nt][3] + bi1;
                    float2 r0 = make_float2(1.f / (1.f + __expf(-s0)), 1.f / (1.f + __expf(-s1)));
                    float2 r1 = make_float2(1.f / (1.f + __expf(-s2)), 1.f / (1.f + __expf(-s3)));
                    *(float2*)(out + ((size_t)b0 * N_INST + i) * N_NOTES + n) = r0;
                    *(float2*)(out + ((size_t)(b0 + 8) * N_INST + i) * N_NOTES + n) = r1;
                }
            }
        }
    }
}

// ---------------------------------------------------------------------------
extern "C" void kernel_launch(void* const* d_in, const int* in_sizes, int n_in,
                              void* d_out, int out_size)
{
    const float* data = (const float*)d_in[0];
    const float* w1   = (const float*)d_in[1];
    const float* b1   = (const float*)d_in[2];
    const float* w2   = (const float*)d_in[3];
    const float* b2   = (const float*)d_in[4];
    const float* wfc  = (const float*)d_in[5];
    const float* bfc  = (const float*)d_in[6];
    float* out = (float*)d_out;

    cudaFuncSetAttribute(fused_kernel, cudaFuncAttributeMaxDynamicSharedMemorySize, SMEM_TOTAL);
    fused_kernel<<<N_INST, 512, SMEM_TOTAL>>>(data, w1, b1, w2, b2, wfc, bfc, out);
}

// round 8
// speedup vs baseline: 1.3274x; 1.3274x over previous
#include <cuda_runtime.h>
#include <cuda_bf16.h>
#include <cstdint>

// Problem dims
#define N_INST 128
#define N_NOTES 88
#define BATCH 64
#define TLEN 201
#define FLEN 52
#define T2 197
#define F2 48
#define FEAT (T2 * F2)  // 9456
#define KC 48
#define NCHUNK 197

typedef unsigned long long ull;

// X split into bf16 hi/lo planes, [i][b][k]
__device__ __nv_bfloat16 g_Xhi[(size_t)N_INST * BATCH * FEAT];
__device__ __nv_bfloat16 g_Xlo[(size_t)N_INST * BATCH * FEAT];

// ---------------------------------------------------------------------------
// helpers
// ---------------------------------------------------------------------------
__device__ __forceinline__ uint32_t smem_u32(const void* p) {
    uint32_t a;
    asm("{ .reg .u64 t; cvta.to.shared.u64 t, %1; cvt.u32.u64 %0, t; }" : "=r"(a) : "l"(p));
    return a;
}
__device__ __forceinline__ unsigned swz(unsigned off) { return off ^ ((off >> 3) & 0x70); }

__device__ __forceinline__ void cp16(uint32_t dst, const void* src) {
    asm volatile("cp.async.ca.shared.global [%0], [%1], 16;" :: "r"(dst), "l"(src) : "memory");
}
__device__ __forceinline__ void cp16g(uint32_t dst, const void* src) {
    asm volatile("cp.async.cg.shared.global [%0], [%1], 16;" :: "r"(dst), "l"(src) : "memory");
}
__device__ __forceinline__ void cp_commit() { asm volatile("cp.async.commit_group;" ::: "memory"); }
#define CP_WAIT(n) asm volatile("cp.async.wait_group %0;" :: "n"(n) : "memory")

__device__ __forceinline__ void ldsm4(unsigned r[4], uint32_t a) {
    asm volatile("ldmatrix.sync.aligned.m8n8.x4.shared.b16 {%0,%1,%2,%3}, [%4];"
                 : "=r"(r[0]), "=r"(r[1]), "=r"(r[2]), "=r"(r[3]) : "r"(a));
}
__device__ __forceinline__ void ldsm2(unsigned r[2], uint32_t a) {
    asm volatile("ldmatrix.sync.aligned.m8n8.x2.shared.b16 {%0,%1}, [%2];"
                 : "=r"(r[0]), "=r"(r[1]) : "r"(a));
}
__device__ __forceinline__ void mma_bf16(float c[4], const unsigned a[4], const unsigned* b) {
    asm volatile(
        "mma.sync.aligned.m16n8k16.row.col.f32.bf16.bf16.f32 "
        "{%0,%1,%2,%3}, {%4,%5,%6,%7}, {%8,%9}, {%0,%1,%2,%3};"
        : "+f"(c[0]), "+f"(c[1]), "+f"(c[2]), "+f"(c[3])
        : "r"(a[0]), "r"(a[1]), "r"(a[2]), "r"(a[3]), "r"(b[0]), "r"(b[1]));
}
__device__ __forceinline__ unsigned cvt_bf16x2(float lo, float hi) {
    unsigned d;
    asm("cvt.rn.bf16x2.f32 %0, %1, %2;" : "=r"(d) : "f"(hi), "f"(lo));
    return d;
}
__device__ __forceinline__ ull pack2(float lo, float hi) {
    ull r;
    asm("mov.b64 %0, {%1, %2};" : "=l"(r) : "f"(lo), "f"(hi));
    return r;
}
__device__ __forceinline__ void unpack2(ull v, float& lo, float& hi) {
    asm("mov.b64 {%0, %1}, %2;" : "=f"(lo), "=f"(hi) : "l"(v));
}
__device__ __forceinline__ ull ffma2(ull a, ull b, ull c) {
    ull d;
    asm("fma.rn.f32x2 %0, %1, %2, %3;" : "=l"(d) : "l"(a), "l"(b), "l"(c));
    return d;
}

// ---------------------------------------------------------------------------
// Conv kernel v3: thread = (instrument, batch, 8-col strip). Register-only
// accumulate-on-arrival at both conv levels. No shfl, no smem, no barriers.
// ---------------------------------------------------------------------------
__global__ __launch_bounds__(256) void conv_kernel(
    const float* __restrict__ data,
    const float* __restrict__ w1, const float* __restrict__ b1,
    const float* __restrict__ w2, const float* __restrict__ b2)
{
    const int idx = blockIdx.x * 256 + threadIdx.x;   // 0..49151
    const int s = idx % 6;                            // strip: output cols 8s..8s+7
    const int p = idx / 6;
    const int b = p & 63;
    const int i = p >> 6;

    ull W1p[9], W2p[9];
#pragma unroll
    for (int k = 0; k < 9; ++k) {
        float a = w1[i * 9 + k]; W1p[k] = pack2(a, a);
        float c = w2[i * 9 + k]; W2p[k] = pack2(c, c);
    }
    const float b1v = b1[i], b2v = b2[i];
    const ull B1p = pack2(b1v, b1v);
    const ull B2p = pack2(b2v, b2v);

    const float* dptr = data + (size_t)b * TLEN * FLEN + 8 * s;
    unsigned short* xh = (unsigned short*)(g_Xhi + ((size_t)i * BATCH + b) * FEAT) + 8 * s;
    unsigned short* xl = (unsigned short*)(g_Xlo + ((size_t)i * BATCH + b) * FEAT) + 8 * s;

    // conv1 accumulators: 3 rows in flight x 5 col-pairs (cols 8s..8s+9)
    // conv2 accumulators: 3 rows in flight x 4 col-pairs (cols 8s..8s+7)
    ull ca[3][5], u[3][4];

#pragma unroll 3
    for (int r = 0; r < TLEN; ++r) {
        const int s0 = r % 3;        // conv1 row r (assign)
        const int s1 = (r + 2) % 3;  // conv1 row r-1
        const int s2 = (r + 1) % 3;  // conv1 row r-2 (completes this iter)

        // load data row r: 12 floats
        const float* rp = dptr + (size_t)r * FLEN;
        float4 A = *(const float4*)rp;
        float4 Bv = *(const float4*)(rp + 4);
        float4 Cv = *(const float4*)(rp + 8);
        ull E[6], O[5];
        E[0] = pack2(A.x, A.y);  E[1] = pack2(A.z, A.w);
        E[2] = pack2(Bv.x, Bv.y); E[3] = pack2(Bv.z, Bv.w);
        E[4] = pack2(Cv.x, Cv.y); E[5] = pack2(Cv.z, Cv.w);
        O[0] = pack2(A.y, A.z);  O[1] = pack2(A.w, Bv.x);
        O[2] = pack2(Bv.y, Bv.z); O[3] = pack2(Bv.w, Cv.x);
        O[4] = pack2(Cv.y, Cv.z);

        // conv1 contributions: row r assigned (w1 row 0), rows r-1/r-2 accumulated
#pragma unroll
        for (int q = 0; q < 5; ++q) {
            ca[s0][q] = ffma2(W1p[2], E[q + 1], ffma2(W1p[1], O[q], ffma2(W1p[0], E[q], B1p)));
            ca[s1][q] = ffma2(W1p[5], E[q + 1], ffma2(W1p[4], O[q], ffma2(W1p[3], E[q], ca[s1][q])));
            ca[s2][q] = ffma2(W1p[8], E[q + 1], ffma2(W1p[7], O[q], ffma2(W1p[6], E[q], ca[s2][q])));
        }

        if (r >= 2) {
            // conv1 row rc = r-2 complete in ca[s2]: relu -> pair views
            float g[10];
#pragma unroll
            for (int q = 0; q < 5; ++q) {
                unpack2(ca[s2][q], g[2 * q], g[2 * q + 1]);
                g[2 * q] = fmaxf(g[2 * q], 0.f);
                g[2 * q + 1] = fmaxf(g[2 * q + 1], 0.f);
            }
            ull pe[5], po[4];
#pragma unroll
            for (int q = 0; q < 5; ++q) pe[q] = pack2(g[2 * q], g[2 * q + 1]);
#pragma unroll
            for (int q = 0; q < 4; ++q) po[q] = pack2(g[2 * q + 1], g[2 * q + 2]);

            // conv2: row rc assigned (w2 row 0, slot s2), row rc-1 (slot s0), rc-2 (slot s1)
#pragma unroll
            for (int q = 0; q < 4; ++q) {
                u[s2][q] = ffma2(W2p[2], pe[q + 1], ffma2(W2p[1], po[q], ffma2(W2p[0], pe[q], B2p)));
                u[s0][q] = ffma2(W2p[5], pe[q + 1], ffma2(W2p[4], po[q], ffma2(W2p[3], pe[q], u[s0][q])));
                u[s1][q] = ffma2(W2p[8], pe[q + 1], ffma2(W2p[7], po[q], ffma2(W2p[6], pe[q], u[s1][q])));
            }

            if (r >= 4) {
                // conv2 row tc = r-4 complete in u[s1]: relu, hi/lo split, store
                unsigned hi[4], lo[4];
#pragma unroll
                for (int q = 0; q < 4; ++q) {
                    float h0, h1;
                    unpack2(u[s1][q], h0, h1);
                    h0 = fmaxf(h0, 0.f); h1 = fmaxf(h1, 0.f);
                    unsigned ub0 = __float_as_uint(h0), ub1 = __float_as_uint(h1);
                    hi[q] = __byte_perm(ub0, ub1, 0x7632);
                    float r0 = h0 - __uint_as_float(ub0 & 0xffff0000u);
                    float r1 = h1 - __uint_as_float(ub1 & 0xffff0000u);
                    lo[q] = cvt_bf16x2(r0, r1);
                }
                const int off = (r - 4) * F2;
                *(uint4*)(xh + off) = make_uint4(hi[0], hi[1], hi[2], hi[3]);
                *(uint4*)(xl + off) = make_uint4(lo[0], lo[1], lo[2], lo[3]);
            }
        }
    }
}

// ---------------------------------------------------------------------------
// FC kernel (R5, proven 190us): one CTA / instrument. mma.sync bf16 3-term.
// 4-stage cp.async ring for W fp32 + X bf16; W converted in-smem 1 chunk ahead.
// ---------------------------------------------------------------------------
#define WF32_STAGE 16896                  // 88 rows x 192B
#define WF32_OFF 0
#define X_OFF (4 * WF32_STAGE)            // 67584
#define X_STAGE 16384
#define XLO_REL 8192
#define WB_OFF (X_OFF + 4 * X_STAGE)      // 133120
#define WB_STAGE 24576
#define WLO_REL 12288
#define SMEM_TOTAL (WB_OFF + 2 * WB_STAGE)  // 182272

__global__ __launch_bounds__(256, 1) void fc_kernel(
    const float* __restrict__ wfc,
    const float* __restrict__ bfc,
    float* __restrict__ out)
{
    extern __shared__ char sm[];
    const uint32_t sbase = smem_u32(sm);
    const int i = blockIdx.x;
    const int tid = threadIdx.x;
    const int lane = tid & 31;
    const int wid = tid >> 5;
    const int warp_m = wid >> 2;
    const int warp_n = wid & 3;

    // zero bf16-W buffers once (pad rows 88..95 never overwritten)
    for (int o = tid * 16; o < 2 * WB_STAGE; o += 256 * 16)
        *(uint4*)(sm + WB_OFF + o) = make_uint4(0, 0, 0, 0);

    const float* Wp = wfc + (size_t)i * N_NOTES * FEAT;
    const __nv_bfloat16* Xhp = g_Xhi + (size_t)i * BATCH * FEAT;
    const __nv_bfloat16* Xlp = g_Xlo + (size_t)i * BATCH * FEAT;

    auto prefetch = [&](int c) {
        const int k0 = c * KC;
        const int st = c & 3;
        const uint32_t wdst = sbase + WF32_OFF + st * WF32_STAGE;
#pragma unroll
        for (int s = 0; s < 4; ++s) {
            int idx = tid + s * 256;
            int row = idx / 12, q = idx % 12;
            cp16g(wdst + idx * 16, Wp + (size_t)row * FEAT + k0 + q * 4);
        }
        if (tid < 32) {
            int idx = 1024 + tid;
            int row = idx / 12, q = idx % 12;
            cp16g(wdst + idx * 16, Wp + (size_t)row * FEAT + k0 + q * 4);
        }
        const uint32_t xdst = sbase + X_OFF + st * X_STAGE;
#pragma unroll
        for (int s = 0; s < 3; ++s) {
            int idx = tid + s * 256;
            int half = idx >= 384;
            int e = half ? idx - 384 : idx;
            int r = e / 6, q = e % 6;
            const __nv_bfloat16* src = (half ? Xlp : Xhp) + (size_t)r * FEAT + k0 + q * 8;
            cp16(xdst + (half ? XLO_REL : 0) + swz(r * 128 + q * 16), src);
        }
        cp_commit();
    };

    auto convert = [&](int c) {
        const char* src = sm + WF32_OFF + (c & 3) * WF32_STAGE;
        char* dhi = sm + WB_OFF + (c & 1) * WB_STAGE;
        char* dlo = dhi + WLO_REL;
#pragma unroll
        for (int s = 0; s < 5; ++s) {
            int idx = tid + s * 256;
            if (idx < 1056) {
                int row = idx / 12, q = idx % 12;
                float4 v = *(const float4*)(src + idx * 16);
                unsigned ax = __float_as_uint(v.x), ay = __float_as_uint(v.y);
                unsigned az = __float_as_uint(v.z), aw = __float_as_uint(v.w);
                unsigned hi0 = __byte_perm(ax, ay, 0x7632);
                unsigned hi1 = __byte_perm(az, aw, 0x7632);
                float rx = v.x - __uint_as_float(ax & 0xffff0000u);
                float ry = v.y - __uint_as_float(ay & 0xffff0000u);
                float rz = v.z - __uint_as_float(az & 0xffff0000u);
                float rw = v.w - __uint_as_float(aw & 0xffff0000u);
                unsigned lo0 = cvt_bf16x2(rx, ry);
                unsigned lo1 = cvt_bf16x2(rz, rw);
                unsigned off = swz(row * 128 + q * 8);
                *(uint2*)(dhi + off) = make_uint2(hi0, hi1);
                *(uint2*)(dlo + off) = make_uint2(lo0, lo1);
            }
        }
    };

    float acc[2][3][4];
#pragma unroll
    for (int mt = 0; mt < 2; ++mt)
#pragma unroll
        for (int nt = 0; nt < 3; ++nt)
#pragma unroll
            for (int r = 0; r < 4; ++r) acc[mt][nt][r] = 0.f;

    const int a_row = lane & 15;
    const int a_colb = (lane >> 4) << 4;
    const int b4_row = (lane & 7) + ((lane >> 4) << 3);
    const int b4_colb = ((lane >> 3) & 1) << 4;
    const int b2_row = lane & 7;
    const int b2_colb = ((lane >> 3) & 1) << 4;

    prefetch(0); prefetch(1); prefetch(2);
    CP_WAIT(2);
    __syncthreads();
    convert(0);

    for (int c = 0; c < NCHUNK; ++c) {
        if (c + 3 < NCHUNK) prefetch(c + 3);
        if (c < NCHUNK - 3)      { CP_WAIT(2); }
        else if (c == NCHUNK - 3) { CP_WAIT(1); }
        else                      { CP_WAIT(0); }
        __syncthreads();
        if (c + 1 < NCHUNK) convert(c + 1);

        const uint32_t xb = sbase + X_OFF + (c & 3) * X_STAGE;
        const uint32_t wb = sbase + WB_OFF + (c & 1) * WB_STAGE;
#pragma unroll
        for (int ks = 0; ks < 3; ++ks) {
            const int kb = ks * 32;
            unsigned ahi[2][4], alo[2][4];
#pragma unroll
            for (int mt = 0; mt < 2; ++mt) {
                int m0 = warp_m * 32 + mt * 16;
                unsigned off = swz((m0 + a_row) * 128 + kb + a_colb);
                ldsm4(ahi[mt], xb + off);
                ldsm4(alo[mt], xb + XLO_REL + off);
            }
            const int n0 = warp_n * 24;
            unsigned bh[3][2], bl[3][2];
            {
                unsigned off4 = swz((n0 + b4_row) * 128 + kb + b4_colb);
                ldsm4(&bh[0][0], wb + off4);
                ldsm4(&bl[0][0], wb + WLO_REL + off4);
                unsigned off2 = swz((n0 + 16 + b2_row) * 128 + kb + b2_colb);
                ldsm2(bh[2], wb + off2);
                ldsm2(bl[2], wb + WLO_REL + off2);
            }
#pragma unroll
            for (int nt = 0; nt < 3; ++nt) {
#pragma unroll
                for (int mt = 0; mt < 2; ++mt) {
                    mma_bf16(acc[mt][nt], ahi[mt], bh[nt]);
                    mma_bf16(acc[mt][nt], ahi[mt], bl[nt]);
                    mma_bf16(acc[mt][nt], alo[mt], bh[nt]);
                }
            }
        }
    }

    // epilogue: bias + sigmoid + store out[b][i][n]
#pragma unroll
    for (int mt = 0; mt < 2; ++mt) {
        int b0 = warp_m * 32 + mt * 16 + (lane >> 2);
#pragma unroll
        for (int nt = 0; nt < 3; ++nt) {
            int n = warp_n * 24 + nt * 8 + 2 * (lane & 3);
            if (n < N_NOTES) {
                float bi0 = bfc[i * N_NOTES + n];
                float bi1 = bfc[i * N_NOTES + n + 1];
                float s0 = acc[mt][nt][0] + bi0;
                float s1 = acc[mt][nt][1] + bi1;
                float s2 = acc[mt][nt][2] + bi0;
                float s3 = acc[mt][nt][3] + bi1;
                float2 r0 = make_float2(1.f / (1.f + __expf(-s0)), 1.f / (1.f + __expf(-s1)));
                float2 r1 = make_float2(1.f / (1.f + __expf(-s2)), 1.f / (1.f + __expf(-s3)));
                *(float2*)(out + ((size_t)b0 * N_INST + i) * N_NOTES + n) = r0;
                *(float2*)(out + ((size_t)(b0 + 8) * N_INST + i) * N_NOTES + n) = r1;
            }
        }
    }
}

// ---------------------------------------------------------------------------
extern "C" void kernel_launch(void* const* d_in, const int* in_sizes, int n_in,
                              void* d_out, int out_size)
{
    const float* data = (const float*)d_in[0];
    const float* w1   = (const float*)d_in[1];
    const float* b1   = (const float*)d_in[2];
    const float* w2   = (const float*)d_in[3];
    const float* b2   = (const float*)d_in[4];
    const float* wfc  = (const float*)d_in[5];
    const float* bfc  = (const float*)d_in[6];
    float* out = (float*)d_out;

    cudaFuncSetAttribute(fc_kernel, cudaFuncAttributeMaxDynamicSharedMemorySize, SMEM_TOTAL);

    conv_kernel<<<192, 256>>>(data, w1, b1, w2, b2);
    fc_kernel<<<N_INST, 256, SMEM_TOTAL>>>(wfc, bfc, out);
}

// round 10
// speedup vs baseline: 1.7651x; 1.3298x over previous
#include <cuda_runtime.h>
#include <cuda_bf16.h>
#include <cstdint>

// Problem dims
#define N_INST 128
#define N_NOTES 88
#define BATCH 64
#define TLEN 201
#define FLEN 52
#define T2 197
#define F2 48
#define FEAT (T2 * F2)
#define KC 48
#define NCHUNK 197

// ---------------------------------------------------------------------------
// smem layout
// ---------------------------------------------------------------------------
#define WF32_STAGE 16896                   // 88 rows x 192B fp32 W
#define WF32_OFF 0
#define WB_OFF (4 * WF32_STAGE)            // 67584: bf16 W hi/lo double buffer
#define WB_STAGE 24576
#define WLO_REL 12288
#define X_OFF (WB_OFF + 2 * WB_STAGE)      // 116736: X hi/lo double buffer
#define X_STAGE 16384
#define XLO_REL 8192
#define SMEM_TOTAL (X_OFF + 2 * X_STAGE)   // 149504

// ---------------------------------------------------------------------------
// helpers
// ---------------------------------------------------------------------------
__device__ __forceinline__ uint32_t smem_u32(const void* p) {
    uint32_t a;
    asm("{ .reg .u64 t; cvta.to.shared.u64 t, %1; cvt.u32.u64 %0, t; }" : "=r"(a) : "l"(p));
    return a;
}
__device__ __forceinline__ unsigned swz(unsigned off) { return off ^ ((off >> 3) & 0x70); }

__device__ __forceinline__ void cp16g(uint32_t dst, const void* src) {
    asm volatile("cp.async.cg.shared.global [%0], [%1], 16;" :: "r"(dst), "l"(src) : "memory");
}
__device__ __forceinline__ void cp_commit() { asm volatile("cp.async.commit_group;" ::: "memory"); }
#define CP_WAIT(n) asm volatile("cp.async.wait_group %0;" :: "n"(n) : "memory")
#define TAILWAIT(c) do { \
    if ((c) < NCHUNK - 3)       { CP_WAIT(2); } \
    else if ((c) == NCHUNK - 3) { CP_WAIT(1); } \
    else                        { CP_WAIT(0); } \
} while (0)

__device__ __forceinline__ void ldsm4(unsigned r[4], uint32_t a) {
    asm volatile("ldmatrix.sync.aligned.m8n8.x4.shared.b16 {%0,%1,%2,%3}, [%4];"
                 : "=r"(r[0]), "=r"(r[1]), "=r"(r[2]), "=r"(r[3]) : "r"(a));
}
__device__ __forceinline__ void ldsm2(unsigned r[2], uint32_t a) {
    asm volatile("ldmatrix.sync.aligned.m8n8.x2.shared.b16 {%0,%1}, [%2];"
                 : "=r"(r[0]), "=r"(r[1]) : "r"(a));
}
__device__ __forceinline__ void mma_bf16(float c[4], const unsigned a[4], const unsigned* b) {
    asm volatile(
        "mma.sync.aligned.m16n8k16.row.col.f32.bf16.bf16.f32 "
        "{%0,%1,%2,%3}, {%4,%5,%6,%7}, {%8,%9}, {%0,%1,%2,%3};"
        : "+f"(c[0]), "+f"(c[1]), "+f"(c[2]), "+f"(c[3])
        : "r"(a[0]), "r"(a[1]), "r"(a[2]), "r"(a[3]), "r"(b[0]), "r"(b[1]));
}
__device__ __forceinline__ unsigned cvt_bf16x2(float lo, float hi) {
    unsigned d;
    asm("cvt.rn.bf16x2.f32 %0, %1, %2;" : "=r"(d) : "f"(hi), "f"(lo));
    return d;
}
__device__ __forceinline__ void sts128(uint32_t a, unsigned r0, unsigned r1, unsigned r2, unsigned r3) {
    asm volatile("st.shared.v4.b32 [%0], {%1,%2,%3,%4};" :: "r"(a), "r"(r0), "r"(r1), "r"(r2), "r"(r3) : "memory");
}

// ---------------------------------------------------------------------------
// Producer conv iteration (scalar, accumulate-on-arrival, R8-proven math).
// Strip of 8 output cols (10-col conv1 window, 12-col data window).
// Slots: S0 = r%3 (assign), S1 = (r+2)%3, S2 = (r+1)%3 (conv1 completes).
// ---------------------------------------------------------------------------
template <int S0, int S1, int S2>
__device__ __forceinline__ void conv_iter(
    int r, bool do_c2, bool emit,
    float (&ca)[3][10], float (&u)[3][8],
    const float* __restrict__ dptr,
    const float* W1, const float* W2, float B1, float B2,
    unsigned (&hi)[4], unsigned (&lo)[4])
{
    const float* rp = dptr + (size_t)r * FLEN;
    float4 A = *(const float4*)rp;
    float4 Bv = *(const float4*)(rp + 4);
    float4 Cv = *(const float4*)(rp + 8);
    float d[12] = {A.x, A.y, A.z, A.w, Bv.x, Bv.y, Bv.z, Bv.w, Cv.x, Cv.y, Cv.z, Cv.w};

#pragma unroll
    for (int j = 0; j < 10; ++j) {
        ca[S0][j] = fmaf(W1[2], d[j + 2], fmaf(W1[1], d[j + 1], fmaf(W1[0], d[j], B1)));
        ca[S1][j] = fmaf(W1[5], d[j + 2], fmaf(W1[4], d[j + 1], fmaf(W1[3], d[j], ca[S1][j])));
        ca[S2][j] = fmaf(W1[8], d[j + 2], fmaf(W1[7], d[j + 1], fmaf(W1[6], d[j], ca[S2][j])));
    }
    if (do_c2) {
        float g[10];
#pragma unroll
        for (int j = 0; j < 10; ++j) g[j] = fmaxf(ca[S2][j], 0.f);
#pragma unroll
        for (int j = 0; j < 8; ++j) {
            u[S2][j] = fmaf(W2[2], g[j + 2], fmaf(W2[1], g[j + 1], fmaf(W2[0], g[j], B2)));
            u[S0][j] = fmaf(W2[5], g[j + 2], fmaf(W2[4], g[j + 1], fmaf(W2[3], g[j], u[S0][j])));
            u[S1][j] = fmaf(W2[8], g[j + 2], fmaf(W2[7], g[j + 1], fmaf(W2[6], g[j], u[S1][j])));
        }
        if (emit) {
#pragma unroll
            for (int q = 0; q < 4; ++q) {
                float h0 = fmaxf(u[S1][2 * q], 0.f);
                float h1 = fmaxf(u[S1][2 * q + 1], 0.f);
                unsigned ub0 = __float_as_uint(h0), ub1 = __float_as_uint(h1);
                hi[q] = __byte_perm(ub0, ub1, 0x7632);
                float r0 = h0 - __uint_as_float(ub0 & 0xffff0000u);
                float r1 = h1 - __uint_as_float(ub1 & 0xffff0000u);
                lo[q] = cvt_bf16x2(r0, r1);
            }
        }
    }
}

// ---------------------------------------------------------------------------
// Fused kernel: one CTA / instrument, 512 threads.
// Warps 0-3: MMA consumers (warp tile 64x24). Warps 4-15: conv producers.
// All threads share the W cp.async ring + fp32->bf16 conversion.
// ---------------------------------------------------------------------------
__global__ __launch_bounds__(512, 1) void fused_kernel(
    const float* __restrict__ data,
    const float* __restrict__ w1, const float* __restrict__ b1,
    const float* __restrict__ w2, const float* __restrict__ b2,
    const float* __restrict__ wfc,
    const float* __restrict__ bfc,
    float* __restrict__ out)
{
    extern __shared__ char sm[];
    const uint32_t sbase = smem_u32(sm);
    const int i = blockIdx.x;
    const int tid = threadIdx.x;
    const int lane = tid & 31;
    const int wid = tid >> 5;

    // zero bf16-W buffers (pad note rows 88..95 stay zero forever)
    for (int o = tid * 16; o < 2 * WB_STAGE; o += 512 * 16)
        *(uint4*)(sm + WB_OFF + o) = make_uint4(0, 0, 0, 0);

    const float* Wp = wfc + (size_t)i * N_NOTES * FEAT;

    // ---- shared W pipeline (all 512 threads take their share) ----
    auto prefetchW = [&](int c) {
        const int k0 = c * KC;
        const uint32_t wdst = sbase + WF32_OFF + (c & 3) * WF32_STAGE;
#pragma unroll
        for (int s = 0; s < 2; ++s) {
            int idx = tid + s * 512;
            cp16g(wdst + idx * 16, Wp + (size_t)(idx / 12) * FEAT + k0 + (idx % 12) * 4);
        }
        if (tid < 32) {
            int idx = 1024 + tid;
            cp16g(wdst + idx * 16, Wp + (size_t)(idx / 12) * FEAT + k0 + (idx % 12) * 4);
        }
        cp_commit();
    };
    auto convertW = [&](int c) {
        const char* src = sm + WF32_OFF + (c & 3) * WF32_STAGE;
        char* dhi = sm + WB_OFF + (c & 1) * WB_STAGE;
        char* dlo = dhi + WLO_REL;
#pragma unroll
        for (int s = 0; s < 3; ++s) {
            int idx = tid + s * 512;
            if (idx < 1056) {
                int row = idx / 12, q = idx % 12;
                float4 v = *(const float4*)(src + idx * 16);
                unsigned ax = __float_as_uint(v.x), ay = __float_as_uint(v.y);
                unsigned az = __float_as_uint(v.z), aw = __float_as_uint(v.w);
                unsigned hi0 = __byte_perm(ax, ay, 0x7632);
                unsigned hi1 = __byte_perm(az, aw, 0x7632);
                float rx = v.x - __uint_as_float(ax & 0xffff0000u);
                float ry = v.y - __uint_as_float(ay & 0xffff0000u);
                float rz = v.z - __uint_as_float(az & 0xffff0000u);
                float rw = v.w - __uint_as_float(aw & 0xffff0000u);
                unsigned lo0 = cvt_bf16x2(rx, ry);
                unsigned lo1 = cvt_bf16x2(rz, rw);
                unsigned off = swz(row * 128 + q * 8);
                *(uint2*)(dhi + off) = make_uint2(hi0, hi1);
                *(uint2*)(dlo + off) = make_uint2(lo0, lo1);
            }
        }
    };

    if (tid < 128) {
        // ================= CONSUMERS (warps 0-3) =================
        const int n0 = wid * 24;
        float acc[4][3][4];
#pragma unroll
        for (int mt = 0; mt < 4; ++mt)
#pragma unroll
            for (int nt = 0; nt < 3; ++nt)
#pragma unroll
                for (int r = 0; r < 4; ++r) acc[mt][nt][r] = 0.f;

        const int a_row = lane & 15;
        const int a_colb = (lane >> 4) << 4;
        const int b4_row = (lane & 7) + ((lane >> 4) << 3);
        const int b4_colb = ((lane >> 3) & 1) << 4;
        const int b2_row = lane & 7;
        const int b2_colb = ((lane >> 3) & 1) << 4;

        prefetchW(0); prefetchW(1); prefetchW(2);
        CP_WAIT(2);
        __syncthreads();
        convertW(0);

        for (int c = 0; c < NCHUNK; ++c) {
            if (c + 3 < NCHUNK) prefetchW(c + 3);
            TAILWAIT(c);
            __syncthreads();
            if (c + 1 < NCHUNK) convertW(c + 1);

            const uint32_t xb = sbase + X_OFF + (c & 1) * X_STAGE;
            const uint32_t wb = sbase + WB_OFF + (c & 1) * WB_STAGE;
#pragma unroll
            for (int ks = 0; ks < 3; ++ks) {
                const int kb = ks * 32;
                unsigned bh[3][2], bl[3][2];
                unsigned off4 = swz((n0 + b4_row) * 128 + kb + b4_colb);
                ldsm4(&bh[0][0], wb + off4);
                ldsm4(&bl[0][0], wb + WLO_REL + off4);
                unsigned off2 = swz((n0 + 16 + b2_row) * 128 + kb + b2_colb);
                ldsm2(bh[2], wb + off2);
                ldsm2(bl[2], wb + WLO_REL + off2);
#pragma unroll
                for (int mt = 0; mt < 4; ++mt) {
                    unsigned ahi[4], alo[4];
                    unsigned offA = swz((mt * 16 + a_row) * 128 + kb + a_colb);
                    ldsm4(ahi, xb + offA);
                    ldsm4(alo, xb + XLO_REL + offA);
#pragma unroll
                    for (int nt = 0; nt < 3; ++nt) {
                        mma_bf16(acc[mt][nt], ahi, bh[nt]);
                        mma_bf16(acc[mt][nt], ahi, bl[nt]);
                        mma_bf16(acc[mt][nt], alo, bh[nt]);
                    }
                }
            }
        }

        // epilogue: bias + sigmoid + store out[b][i][n]
#pragma unroll
        for (int mt = 0; mt < 4; ++mt) {
            int b0 = mt * 16 + (lane >> 2);
#pragma unroll
            for (int nt = 0; nt < 3; ++nt) {
                int n = n0 + nt * 8 + 2 * (lane & 3);
                if (n < N_NOTES) {
                    float bi0 = bfc[i * N_NOTES + n];
                    float bi1 = bfc[i * N_NOTES + n + 1];
                    float s0 = acc[mt][nt][0] + bi0;
                    float s1 = acc[mt][nt][1] + bi1;
                    float s2 = acc[mt][nt][2] + bi0;
                    float s3 = acc[mt][nt][3] + bi1;
                    float2 r0 = make_float2(1.f / (1.f + __expf(-s0)), 1.f / (1.f + __expf(-s1)));
                    float2 r1 = make_float2(1.f / (1.f + __expf(-s2)), 1.f / (1.f + __expf(-s3)));
                    *(float2*)(out + ((size_t)b0 * N_INST + i) * N_NOTES + n) = r0;
                    *(float2*)(out + ((size_t)(b0 + 8) * N_INST + i) * N_NOTES + n) = r1;
                }
            }
        }
    } else {
        // ================= PRODUCERS (warps 4-15) =================
        const int ptid = tid - 128;     // 0..383
        const int s = ptid % 6;         // strip: output cols 8s..8s+7
        const int b = ptid / 6;         // batch 0..63

        float W1[9], W2[9];
#pragma unroll
        for (int k = 0; k < 9; ++k) { W1[k] = w1[i * 9 + k]; W2[k] = w2[i * 9 + k]; }
        const float B1 = b1[i], B2 = b2[i];

        const float* dptr = data + (size_t)b * TLEN * FLEN + 8 * s;
        const unsigned xoff = swz(b * 128 + s * 16);

        float ca[3][10], u[3][8];
#pragma unroll
        for (int k = 0; k < 3; ++k) {
#pragma unroll
            for (int j = 0; j < 10; ++j) ca[k][j] = 0.f;
#pragma unroll
            for (int j = 0; j < 8; ++j) u[k][j] = 0.f;
        }
        unsigned hi[4], lo[4];

        auto xstore = [&](int buf) {
            uint32_t xa = sbase + X_OFF + buf * X_STAGE;
            sts128(xa + xoff, hi[0], hi[1], hi[2], hi[3]);
            sts128(xa + XLO_REL + xoff, lo[0], lo[1], lo[2], lo[3]);
        };

        prefetchW(0); prefetchW(1); prefetchW(2);
        // prologue conv: rows 0..4; row 0 completes at r=4 -> X buf 0
        conv_iter<0, 2, 1>(0, false, false, ca, u, dptr, W1, W2, B1, B2, hi, lo);
        conv_iter<1, 0, 2>(1, false, false, ca, u, dptr, W1, W2, B1, B2, hi, lo);
        conv_iter<2, 1, 0>(2, true,  false, ca, u, dptr, W1, W2, B1, B2, hi, lo);
        conv_iter<0, 2, 1>(3, true,  false, ca, u, dptr, W1, W2, B1, B2, hi, lo);
        conv_iter<1, 0, 2>(4, true,  true,  ca, u, dptr, W1, W2, B1, B2, hi, lo);
        xstore(0);
        CP_WAIT(2);
        __syncthreads();
        convertW(0);

#define PBODY(c, S0, S1, S2) do { \
    if ((c) + 3 < NCHUNK) prefetchW((c) + 3); \
    conv_iter<S0, S1, S2>((c) + 5, true, true, ca, u, dptr, W1, W2, B1, B2, hi, lo); \
    TAILWAIT(c); \
    __syncthreads(); \
    if ((c) + 1 < NCHUNK) convertW((c) + 1); \
    xstore(((c) + 1) & 1); \
} while (0)

        for (int c0 = 0; c0 < 195; c0 += 3) {
            PBODY(c0 + 0, 2, 1, 0);
            PBODY(c0 + 1, 0, 2, 1);
            PBODY(c0 + 2, 1, 0, 2);
        }
        PBODY(195, 2, 1, 0);
#undef PBODY
        // final chunk c=196: no conv, no convert
        {
            CP_WAIT(0);
            __syncthreads();
        }
    }
}

// ---------------------------------------------------------------------------
extern "C" void kernel_launch(void* const* d_in, const int* in_sizes, int n_in,
                              void* d_out, int out_size)
{
    const float* data = (const float*)d_in[0];
    const float* w1   = (const float*)d_in[1];
    const float* b1   = (const float*)d_in[2];
    const float* w2   = (const float*)d_in[3];
    const float* b2   = (const float*)d_in[4];
    const float* wfc  = (const float*)d_in[5];
    const float* bfc  = (const float*)d_in[6];
    float* out = (float*)d_out;

    cudaFuncSetAttribute(fused_kernel, cudaFuncAttributeMaxDynamicSharedMemorySize, SMEM_TOTAL);
    fused_kernel<<<N_INST, 512, SMEM_TOTAL>>>(data, w1, b1, w2, b2, wfc, bfc, out);
}